// round 1
// baseline (speedup 1.0000x reference)
#include <cuda_runtime.h>
#include <math.h>

#define N_I 100000
#define N_O 50000
#define FD 32
#define EAD 8
#define NE 100000

// Scratch (allocation-free): accumulators, reused in-place as h after root+sigmoid.
__device__ __align__(16) float g_acc_i[N_I * FD];   // layer-1 indivi agg -> h_indivi
__device__ __align__(16) float g_acc_o[N_O * FD];   // layer-1 org agg    -> h_org
__device__ __align__(16) float g_acc2[N_I];         // layer-2 agg

__device__ __forceinline__ float sigmoidf(float v) {
    return 1.0f / (1.0f + expf(-v));
}

// ---------------------------------------------------------------------------
// Zero all accumulators (float4 grid-stride)
// ---------------------------------------------------------------------------
__global__ void zero_kernel() {
    const float4 z = make_float4(0.f, 0.f, 0.f, 0.f);
    int idx = blockIdx.x * blockDim.x + threadIdx.x;
    int stride = gridDim.x * blockDim.x;
    for (int i = idx; i < N_I * FD / 4; i += stride) ((float4*)g_acc_i)[i] = z;
    for (int i = idx; i < N_O * FD / 4; i += stride) ((float4*)g_acc_o)[i] = z;
    for (int i = idx; i < N_I / 4;      i += stride) ((float4*)g_acc2)[i] = z;
}

// ---------------------------------------------------------------------------
// Layer-1 edge kernel: msg[e,o] = sum_i x_src[src[e],i] * (bm[i,o] + sum_a e[a]*Wm[a,i,o])
// One warp handles U=4 edges; lane = output channel o.
// Wm (8x1024) + bm (1024) staged in shared; 9 LDS amortized over 36 FMA per i-step.
// ---------------------------------------------------------------------------
__global__ __launch_bounds__(256) void edge_msg_kernel(
    const float* __restrict__ x_src,
    const int*   __restrict__ src,
    const int*   __restrict__ dst,
    const float* __restrict__ eattr,
    const float* __restrict__ Wm,
    const float* __restrict__ bm,
    int which)                         // 0 -> g_acc_i, 1 -> g_acc_o
{
    __shared__ float sWm[EAD * FD * FD];   // 32 KB
    __shared__ float sbm[FD * FD];         // 4 KB

    float* acc = (which == 0) ? g_acc_i : g_acc_o;

    const int t = threadIdx.x;
    // cooperative load: 8192 floats = 2048 float4 (8 per thread), 1024 floats = 256 float4
    #pragma unroll
    for (int k = 0; k < 8; k++)
        ((float4*)sWm)[t + k * 256] = ((const float4*)Wm)[t + k * 256];
    ((float4*)sbm)[t] = ((const float4*)bm)[t];
    __syncthreads();

    const int lane = t & 31;
    const int warp = t >> 5;
    const int U = 4;
    const int e0 = (blockIdx.x * 8 + warp) * U;
    if (e0 >= NE) return;

    float xreg[U];
    float er[U][EAD];
    float msg[U];
    int   dsts[U];

    #pragma unroll
    for (int u = 0; u < U; u++) {
        int e = e0 + u;
        bool valid = (e < NE);
        int s = valid ? src[e] : 0;
        dsts[u] = valid ? dst[e] : -1;
        xreg[u] = x_src[s * FD + lane];                 // coalesced 128B row
        float ev = (valid && lane < EAD) ? eattr[e * EAD + lane] : 0.f;
        #pragma unroll
        for (int a = 0; a < EAD; a++)
            er[u][a] = __shfl_sync(0xffffffffu, ev, a);
        msg[u] = 0.f;
    }

    #pragma unroll 4
    for (int i = 0; i < FD; i++) {
        float bmv = sbm[i * FD + lane];
        float xb[U], w[U];
        #pragma unroll
        for (int u = 0; u < U; u++) {
            xb[u] = __shfl_sync(0xffffffffu, xreg[u], i);
            w[u]  = bmv;
        }
        #pragma unroll
        for (int a = 0; a < EAD; a++) {
            float wmv = sWm[a * (FD * FD) + i * FD + lane];
            #pragma unroll
            for (int u = 0; u < U; u++)
                w[u] = fmaf(er[u][a], wmv, w[u]);
        }
        #pragma unroll
        for (int u = 0; u < U; u++)
            msg[u] = fmaf(xb[u], w[u], msg[u]);
    }

    #pragma unroll
    for (int u = 0; u < U; u++)
        if (dsts[u] >= 0)
            atomicAdd(&acc[dsts[u] * FD + lane], msg[u]);
}

// ---------------------------------------------------------------------------
// Root + bias + sigmoid, in place over the accumulator:
//   acc[n,:] = sigmoid(acc[n,:] + x[n,:] @ Wr + b)
// Thread per node; Wr in shared (uniform-broadcast LDS).
// ---------------------------------------------------------------------------
__global__ __launch_bounds__(256) void root_kernel(
    const float* __restrict__ x,
    const float* __restrict__ Wr,
    const float* __restrict__ b,
    int N, int which)
{
    __shared__ float sW[FD * FD];
    __shared__ float sb[FD];

    float* acc = (which == 0) ? g_acc_i : g_acc_o;

    const int t = threadIdx.x;
    ((float4*)sW)[t] = ((const float4*)Wr)[t];   // 1024 floats = 256 float4
    if (t < FD) sb[t] = b[t];
    __syncthreads();

    const int n = blockIdx.x * 256 + t;
    if (n >= N) return;

    float xr[FD], o[FD];
    const float4* xp = (const float4*)(x + (size_t)n * FD);
    float4* ap = (float4*)(acc + (size_t)n * FD);

    #pragma unroll
    for (int k = 0; k < FD / 4; k++) {
        float4 v = xp[k];
        xr[4*k] = v.x; xr[4*k+1] = v.y; xr[4*k+2] = v.z; xr[4*k+3] = v.w;
    }
    #pragma unroll
    for (int k = 0; k < FD / 4; k++) {
        float4 v = ap[k];
        o[4*k]   = v.x + sb[4*k];
        o[4*k+1] = v.y + sb[4*k+1];
        o[4*k+2] = v.z + sb[4*k+2];
        o[4*k+3] = v.w + sb[4*k+3];
    }
    #pragma unroll
    for (int i = 0; i < FD; i++) {
        float xv = xr[i];
        #pragma unroll
        for (int j = 0; j < FD; j++)
            o[j] = fmaf(xv, sW[i * FD + j], o[j]);
    }
    #pragma unroll
    for (int k = 0; k < FD / 4; k++) {
        float4 v;
        v.x = sigmoidf(o[4*k]);
        v.y = sigmoidf(o[4*k+1]);
        v.z = sigmoidf(o[4*k+2]);
        v.w = sigmoidf(o[4*k+3]);
        ap[k] = v;
    }
}

// ---------------------------------------------------------------------------
// Layer-2 edge kernel (f_out = 1), warp per edge:
//   c_i = bm2[i] + sum_a e[a]*Wm2[a,i];  s = sum_i h_org[src,i]*c_i;  acc2[dst] += s
// ---------------------------------------------------------------------------
__global__ __launch_bounds__(256) void edge2_kernel(
    const int*   __restrict__ src,
    const int*   __restrict__ dst,
    const float* __restrict__ eattr,
    const float* __restrict__ Wm2,
    const float* __restrict__ bm2)
{
    __shared__ float sW[EAD * FD];   // 256 floats
    __shared__ float sb[FD];

    const int t = threadIdx.x;
    if (t < 64) ((float4*)sW)[t] = ((const float4*)Wm2)[t];
    if (t < FD) sb[t] = bm2[t];
    __syncthreads();

    const int e = (blockIdx.x * 256 + t) >> 5;
    const int lane = t & 31;
    if (e >= NE) return;

    float ev = (lane < EAD) ? eattr[e * EAD + lane] : 0.f;
    float c = sb[lane];
    #pragma unroll
    for (int a = 0; a < EAD; a++)
        c = fmaf(__shfl_sync(0xffffffffu, ev, a), sW[a * FD + lane], c);

    int s = src[e];
    float p = g_acc_o[s * FD + lane] * c;   // g_acc_o now holds h_org
    #pragma unroll
    for (int off = 16; off; off >>= 1)
        p += __shfl_down_sync(0xffffffffu, p, off);

    if (lane == 0)
        atomicAdd(&g_acc2[dst[e]], p);
}

// ---------------------------------------------------------------------------
// Output: out[n] = sigmoid(acc2[n] + h_indivi[n,:] @ Wr2 + b2)   (warp per node)
// ---------------------------------------------------------------------------
__global__ __launch_bounds__(256) void out_kernel(
    const float* __restrict__ Wr2,
    const float* __restrict__ b2,
    float* __restrict__ out)
{
    const int t = threadIdx.x;
    const int n = (blockIdx.x * 256 + t) >> 5;
    const int lane = t & 31;
    if (n >= N_I) return;

    float p = g_acc_i[n * FD + lane] * __ldg(&Wr2[lane]);   // g_acc_i holds h_indivi
    #pragma unroll
    for (int off = 16; off; off >>= 1)
        p += __shfl_down_sync(0xffffffffu, p, off);

    if (lane == 0)
        out[n] = sigmoidf(p + g_acc2[n] + __ldg(&b2[0]));
}

// ---------------------------------------------------------------------------
extern "C" void kernel_launch(void* const* d_in, const int* in_sizes, int n_in,
                              void* d_out, int out_size)
{
    const float* x_indivi = (const float*)d_in[0];
    const float* x_org    = (const float*)d_in[1];
    const int*   src_oi   = (const int*)  d_in[2];
    const int*   dst_oi   = (const int*)  d_in[3];
    const float* ea_oi    = (const float*)d_in[4];
    const int*   src_io   = (const int*)  d_in[5];
    const int*   dst_io   = (const int*)  d_in[6];
    const float* ea_io    = (const float*)d_in[7];
    const float* Wm_oi    = (const float*)d_in[8];
    const float* bm_oi    = (const float*)d_in[9];
    const float* Wr_oi    = (const float*)d_in[10];
    const float* b_oi     = (const float*)d_in[11];
    const float* Wm_io    = (const float*)d_in[12];
    const float* bm_io    = (const float*)d_in[13];
    const float* Wr_io    = (const float*)d_in[14];
    const float* b_io     = (const float*)d_in[15];
    const float* Wm2      = (const float*)d_in[16];
    const float* bm2      = (const float*)d_in[17];
    const float* Wr2      = (const float*)d_in[18];
    const float* b2       = (const float*)d_in[19];
    float* out = (float*)d_out;

    const int EDGE_BLOCKS = (NE + 31) / 32;          // 8 warps * 4 edges per block

    zero_kernel<<<512, 256>>>();
    edge_msg_kernel<<<EDGE_BLOCKS, 256>>>(x_org,    src_oi, dst_oi, ea_oi, Wm_oi, bm_oi, 0);
    edge_msg_kernel<<<EDGE_BLOCKS, 256>>>(x_indivi, src_io, dst_io, ea_io, Wm_io, bm_io, 1);
    root_kernel<<<(N_I + 255) / 256, 256>>>(x_indivi, Wr_oi, b_oi, N_I, 0);
    root_kernel<<<(N_O + 255) / 256, 256>>>(x_org,    Wr_io, b_io, N_O, 1);
    edge2_kernel<<<(NE * 32 + 255) / 256, 256>>>(src_oi, dst_oi, ea_oi, Wm2, bm2);
    out_kernel<<<(N_I * 32 + 255) / 256, 256>>>(Wr2, b2, out);
}